// round 1
// baseline (speedup 1.0000x reference)
#include <cuda_runtime.h>
#include <math.h>

// Problem constants
#define B_  4
#define T_  2048
#define C_  1024
#define H_  16
#define D_  64
#define M_  (B_*T_)     // 8192 rows
#define N3  (3*C_)      // 3072

// Scratch (static device arrays -- allocation-free per harness rules)
__device__ float g_Q[(size_t)B_*H_*T_*D_];   // [B,H,T,D]
__device__ float g_K[(size_t)B_*H_*T_*D_];
__device__ float g_V[(size_t)B_*H_*T_*D_];
__device__ float g_O[(size_t)M_*C_];         // attention output, [B,T,C]

// ---------------------------------------------------------------------------
// Kernel 1: QKV GEMM  (X[8192,1024] @ W[1024,3072] + b) -> scatter to Q/K/V
// 128x128x8 tile, 256 threads, 8x8 register micro-tile.
// ---------------------------------------------------------------------------
__global__ void __launch_bounds__(256) qkv_gemm_kernel(
    const float* __restrict__ X, const float* __restrict__ W,
    const float* __restrict__ bias)
{
    __shared__ float As[8][128];
    __shared__ float Bs[8][128];
    const int tid = threadIdx.x;
    const int m0 = blockIdx.y * 128;
    const int n0 = blockIdx.x * 128;

    const int arow = tid >> 1;            // 0..127
    const int acol = (tid & 1) << 2;      // 0 or 4
    const int brow = tid >> 5;            // 0..7
    const int bcol = (tid & 31) << 2;     // 0..124
    const int ty = tid >> 4;              // 0..15
    const int tx = tid & 15;              // 0..15

    const float* Ag = X + (size_t)(m0 + arow) * C_ + acol;
    const float* Bg = W + (size_t)brow * N3 + n0 + bcol;

    float acc[8][8];
#pragma unroll
    for (int i = 0; i < 8; i++)
#pragma unroll
        for (int j = 0; j < 8; j++) acc[i][j] = 0.f;

    for (int kb = 0; kb < C_; kb += 8) {
        float4 av = *(const float4*)(Ag + kb);
        float4 bv = *(const float4*)(Bg + (size_t)kb * N3);
        __syncthreads();
        As[acol + 0][arow] = av.x;
        As[acol + 1][arow] = av.y;
        As[acol + 2][arow] = av.z;
        As[acol + 3][arow] = av.w;
        *(float4*)&Bs[brow][bcol] = bv;
        __syncthreads();
#pragma unroll
        for (int k = 0; k < 8; k++) {
            float a[8], b[8];
            *(float4*)&a[0] = *(const float4*)&As[k][ty * 8];
            *(float4*)&a[4] = *(const float4*)&As[k][ty * 8 + 4];
            *(float4*)&b[0] = *(const float4*)&Bs[k][tx * 8];
            *(float4*)&b[4] = *(const float4*)&Bs[k][tx * 8 + 4];
#pragma unroll
            for (int i = 0; i < 8; i++)
#pragma unroll
                for (int j = 0; j < 8; j++)
                    acc[i][j] += a[i] * b[j];
        }
    }

    // Epilogue: add bias, scatter to [B,H,T,D]. Each 128-wide n-tile lies
    // entirely inside one of {Q,K,V} since 1024 % 128 == 0.
    const int part = n0 >> 10;
    float* dst = (part == 0) ? g_Q : ((part == 1) ? g_K : g_V);
#pragma unroll
    for (int i = 0; i < 8; i++) {
        const int m = m0 + ty * 8 + i;
        const int bb = m >> 11;
        const int t  = m & 2047;
#pragma unroll
        for (int j = 0; j < 8; j += 4) {
            const int n  = n0 + tx * 8 + j;
            const int cc = n & 1023;
            const int h  = cc >> 6;
            const int d  = cc & 63;
            float4 v;
            v.x = acc[i][j + 0] + bias[n + 0];
            v.y = acc[i][j + 1] + bias[n + 1];
            v.z = acc[i][j + 2] + bias[n + 2];
            v.w = acc[i][j + 3] + bias[n + 3];
            const size_t idx = ((((size_t)bb * H_ + h) * T_) + t) * D_ + d;
            *(float4*)&dst[idx] = v;
        }
    }
}

// ---------------------------------------------------------------------------
// Kernel 2: flash attention. One block = one (b,h) x 64-row q tile.
// 256 threads; 4x4 register tiles for both QK^T and PV; online softmax.
// ---------------------------------------------------------------------------
#define AP 68  // padded row stride (floats) to break smem bank conflicts

__global__ void __launch_bounds__(256) attn_kernel()
{
    extern __shared__ float sm[];
    float* Qs   = sm;               // 64*AP
    float* Ks   = Qs + 64 * AP;
    float* Vs   = Ks + 64 * AP;
    float* Ss   = Vs + 64 * AP;
    float* m_sh = Ss + 64 * AP;     // 64
    float* l_sh = m_sh + 64;        // 64
    float* e_sh = l_sh + 64;        // 64

    const int tid = threadIdx.x;
    const int qi  = blockIdx.x;     // 0..31
    const int bh  = blockIdx.y;     // 0..63

    const float* Qg = g_Q + ((size_t)bh * T_ + qi * 64) * D_;
    const float* Kg = g_K + (size_t)bh * T_ * D_;
    const float* Vg = g_V + (size_t)bh * T_ * D_;

    const int lrow = tid >> 2;            // 0..63
    const int lcol = (tid & 3) << 4;      // 0,16,32,48

    // Load Q tile (64x64, coalesced float4)
    {
        const float4* src = (const float4*)(Qg + lrow * D_ + lcol);
        float4* dstq = (float4*)(Qs + lrow * AP + lcol);
        dstq[0] = src[0]; dstq[1] = src[1]; dstq[2] = src[2]; dstq[3] = src[3];
    }
    if (tid < 64) { m_sh[tid] = -INFINITY; l_sh[tid] = 0.f; }

    const int r = tid >> 4;   // 0..15 -> q rows r*4..r*4+3
    const int c = tid & 15;   // 0..15 -> cols  c*4..c*4+3

    float acc[4][4];
#pragma unroll
    for (int i = 0; i < 4; i++)
#pragma unroll
        for (int j = 0; j < 4; j++) acc[i][j] = 0.f;

    for (int kt = 0; kt < T_ / 64; kt++) {
        __syncthreads();
        // Load K,V tiles
        {
            const float4* ksrc = (const float4*)(Kg + (kt * 64 + lrow) * D_ + lcol);
            const float4* vsrc = (const float4*)(Vg + (kt * 64 + lrow) * D_ + lcol);
            float4* kd = (float4*)(Ks + lrow * AP + lcol);
            float4* vd = (float4*)(Vs + lrow * AP + lcol);
            kd[0] = ksrc[0]; kd[1] = ksrc[1]; kd[2] = ksrc[2]; kd[3] = ksrc[3];
            vd[0] = vsrc[0]; vd[1] = vsrc[1]; vd[2] = vsrc[2]; vd[3] = vsrc[3];
        }
        __syncthreads();

        // S = Q @ K^T  (4x4 register tile per thread)
        float s[4][4];
#pragma unroll
        for (int i = 0; i < 4; i++)
#pragma unroll
            for (int j = 0; j < 4; j++) s[i][j] = 0.f;

#pragma unroll 4
        for (int kk = 0; kk < 64; kk += 4) {
            float4 a[4], b[4];
#pragma unroll
            for (int i = 0; i < 4; i++) a[i] = *(const float4*)(Qs + (r * 4 + i) * AP + kk);
#pragma unroll
            for (int j = 0; j < 4; j++) b[j] = *(const float4*)(Ks + (c * 4 + j) * AP + kk);
#pragma unroll
            for (int i = 0; i < 4; i++)
#pragma unroll
                for (int j = 0; j < 4; j++)
                    s[i][j] += a[i].x * b[j].x + a[i].y * b[j].y
                             + a[i].z * b[j].z + a[i].w * b[j].w;
        }
#pragma unroll
        for (int i = 0; i < 4; i++) {
            float4 v;
            v.x = s[i][0] * 0.125f; v.y = s[i][1] * 0.125f;
            v.z = s[i][2] * 0.125f; v.w = s[i][3] * 0.125f;
            *(float4*)(Ss + (r * 4 + i) * AP + c * 4) = v;
        }
        __syncthreads();

        // Online softmax: 4 lanes per row, each scans 16 elements
        {
            float* row = Ss + lrow * AP + lcol;
            float vals[16];
            float mx = -INFINITY;
#pragma unroll
            for (int q = 0; q < 16; q++) { vals[q] = row[q]; mx = fmaxf(mx, vals[q]); }
            mx = fmaxf(mx, __shfl_xor_sync(0xffffffffu, mx, 1));
            mx = fmaxf(mx, __shfl_xor_sync(0xffffffffu, mx, 2));
            const float m_old = m_sh[lrow];
            const float l_old = l_sh[lrow];
            const float m_new = fmaxf(m_old, mx);
            float ssum = 0.f;
#pragma unroll
            for (int q = 0; q < 16; q++) {
                float p = __expf(vals[q] - m_new);
                row[q] = p;
                ssum += p;
            }
            ssum += __shfl_xor_sync(0xffffffffu, ssum, 1);
            ssum += __shfl_xor_sync(0xffffffffu, ssum, 2);
            const float efac = __expf(m_old - m_new);
            if ((tid & 3) == 0) {
                m_sh[lrow] = m_new;
                l_sh[lrow] = l_old * efac + ssum;
                e_sh[lrow] = efac;
            }
        }
        __syncthreads();

        // Rescale accumulators, then acc += P @ V
#pragma unroll
        for (int i = 0; i < 4; i++) {
            const float f = e_sh[r * 4 + i];
#pragma unroll
            for (int j = 0; j < 4; j++) acc[i][j] *= f;
        }
#pragma unroll 4
        for (int kk = 0; kk < 64; kk += 4) {
            float4 p[4];
#pragma unroll
            for (int i = 0; i < 4; i++) p[i] = *(const float4*)(Ss + (r * 4 + i) * AP + kk);
            const float4 v0 = *(const float4*)(Vs + (kk + 0) * AP + c * 4);
            const float4 v1 = *(const float4*)(Vs + (kk + 1) * AP + c * 4);
            const float4 v2 = *(const float4*)(Vs + (kk + 2) * AP + c * 4);
            const float4 v3 = *(const float4*)(Vs + (kk + 3) * AP + c * 4);
#pragma unroll
            for (int i = 0; i < 4; i++) {
                acc[i][0] += p[i].x * v0.x + p[i].y * v1.x + p[i].z * v2.x + p[i].w * v3.x;
                acc[i][1] += p[i].x * v0.y + p[i].y * v1.y + p[i].z * v2.y + p[i].w * v3.y;
                acc[i][2] += p[i].x * v0.z + p[i].y * v1.z + p[i].z * v2.z + p[i].w * v3.z;
                acc[i][3] += p[i].x * v0.w + p[i].y * v1.w + p[i].z * v2.w + p[i].w * v3.w;
            }
        }
    }

    // Epilogue: normalize and write to [B,T,C]
    const int b = bh >> 4;
    const int h = bh & 15;
#pragma unroll
    for (int i = 0; i < 4; i++) {
        const int t = qi * 64 + r * 4 + i;
        const float inv = 1.f / l_sh[r * 4 + i];
        float4 o;
        o.x = acc[i][0] * inv; o.y = acc[i][1] * inv;
        o.z = acc[i][2] * inv; o.w = acc[i][3] * inv;
        *(float4*)&g_O[((size_t)b * T_ + t) * C_ + h * D_ + c * 4] = o;
    }
}

// ---------------------------------------------------------------------------
// Kernel 3: output projection  (g_O[8192,1024] @ W[1024,1024] + b) -> out
// ---------------------------------------------------------------------------
__global__ void __launch_bounds__(256) proj_gemm_kernel(
    const float* __restrict__ W, const float* __restrict__ bias,
    float* __restrict__ out)
{
    __shared__ float As[8][128];
    __shared__ float Bs[8][128];
    const int tid = threadIdx.x;
    const int m0 = blockIdx.y * 128;
    const int n0 = blockIdx.x * 128;

    const int arow = tid >> 1;
    const int acol = (tid & 1) << 2;
    const int brow = tid >> 5;
    const int bcol = (tid & 31) << 2;
    const int ty = tid >> 4;
    const int tx = tid & 15;

    const float* Ag = g_O + (size_t)(m0 + arow) * C_ + acol;
    const float* Bg = W + (size_t)brow * C_ + n0 + bcol;

    float acc[8][8];
#pragma unroll
    for (int i = 0; i < 8; i++)
#pragma unroll
        for (int j = 0; j < 8; j++) acc[i][j] = 0.f;

    for (int kb = 0; kb < C_; kb += 8) {
        float4 av = *(const float4*)(Ag + kb);
        float4 bv = *(const float4*)(Bg + (size_t)kb * C_);
        __syncthreads();
        As[acol + 0][arow] = av.x;
        As[acol + 1][arow] = av.y;
        As[acol + 2][arow] = av.z;
        As[acol + 3][arow] = av.w;
        *(float4*)&Bs[brow][bcol] = bv;
        __syncthreads();
#pragma unroll
        for (int k = 0; k < 8; k++) {
            float a[8], b[8];
            *(float4*)&a[0] = *(const float4*)&As[k][ty * 8];
            *(float4*)&a[4] = *(const float4*)&As[k][ty * 8 + 4];
            *(float4*)&b[0] = *(const float4*)&Bs[k][tx * 8];
            *(float4*)&b[4] = *(const float4*)&Bs[k][tx * 8 + 4];
#pragma unroll
            for (int i = 0; i < 8; i++)
#pragma unroll
                for (int j = 0; j < 8; j++)
                    acc[i][j] += a[i] * b[j];
        }
    }

#pragma unroll
    for (int i = 0; i < 8; i++) {
        const int m = m0 + ty * 8 + i;
#pragma unroll
        for (int j = 0; j < 8; j += 4) {
            const int n = n0 + tx * 8 + j;
            float4 v;
            v.x = acc[i][j + 0] + bias[n + 0];
            v.y = acc[i][j + 1] + bias[n + 1];
            v.z = acc[i][j + 2] + bias[n + 2];
            v.w = acc[i][j + 3] + bias[n + 3];
            *(float4*)&out[(size_t)m * C_ + n] = v;
        }
    }
}

// ---------------------------------------------------------------------------
// Launch
// ---------------------------------------------------------------------------
#define ATTN_SMEM_BYTES ((4 * 64 * AP + 3 * 64) * (int)sizeof(float))  // 70400

extern "C" void kernel_launch(void* const* d_in, const int* in_sizes, int n_in,
                              void* d_out, int out_size)
{
    (void)in_sizes; (void)n_in; (void)out_size;
    const float* X      = (const float*)d_in[0];
    const float* W_qkv  = (const float*)d_in[1];
    const float* b_qkv  = (const float*)d_in[2];
    const float* W_proj = (const float*)d_in[3];
    const float* b_proj = (const float*)d_in[4];
    float* out = (float*)d_out;

    // Host-side attribute set: not a stream op, capture-safe, idempotent.
    cudaFuncSetAttribute(attn_kernel,
                         cudaFuncAttributeMaxDynamicSharedMemorySize,
                         ATTN_SMEM_BYTES);

    dim3 g1(N3 / 128, M_ / 128);   // (24, 64)
    qkv_gemm_kernel<<<g1, 256>>>(X, W_qkv, b_qkv);

    dim3 g2(T_ / 64, B_ * H_);     // (32, 64)
    attn_kernel<<<g2, 256, ATTN_SMEM_BYTES>>>();

    dim3 g3(C_ / 128, M_ / 128);   // (8, 64)
    proj_gemm_kernel<<<g3, 256>>>(W_proj, b_proj, out);
}

// round 3
// speedup vs baseline: 3.6849x; 3.6849x over previous
#include <cuda_runtime.h>
#include <math.h>
#include <stdint.h>

// Problem constants
#define B_  4
#define T_  2048
#define C_  1024
#define H_  16
#define D_  64
#define M_  (B_*T_)     // 8192
#define N3  (3*C_)      // 3072

// Scratch
__device__ float g_Q[(size_t)M_*C_];   // [B,H,T,D]
__device__ float g_K[(size_t)M_*C_];
__device__ float g_V[(size_t)M_*C_];
__device__ float g_O[(size_t)M_*C_];   // attention out, [B,T,C]

// ---------------------------------------------------------------------------
// Helpers
// ---------------------------------------------------------------------------
__device__ __forceinline__ float f2tf(float x) {
    uint32_t u; asm("cvt.rna.tf32.f32 %0, %1;" : "=r"(u) : "f"(x));
    return __uint_as_float(u);
}
__device__ __forceinline__ void mma_tf32(float c[4], const uint32_t a[4], const uint32_t b[2]) {
    asm volatile("mma.sync.aligned.m16n8k8.row.col.f32.tf32.tf32.f32 "
        "{%0,%1,%2,%3}, {%4,%5,%6,%7}, {%8,%9}, {%0,%1,%2,%3};"
        : "+f"(c[0]), "+f"(c[1]), "+f"(c[2]), "+f"(c[3])
        : "r"(a[0]), "r"(a[1]), "r"(a[2]), "r"(a[3]), "r"(b[0]), "r"(b[1]));
}
__device__ __forceinline__ void cp16(uint32_t dst, const void* src) {
    asm volatile("cp.async.cg.shared.global [%0], [%1], 16;" :: "r"(dst), "l"(src));
}
#define CP_COMMIT() asm volatile("cp.async.commit_group;")
#define CP_WAIT0()  asm volatile("cp.async.wait_group 0;")

// ---------------------------------------------------------------------------
// Shared GEMM core: C[128x128] block tile = A[M,K] @ B[K,N] (both row-major).
// 8 warps, warp tile 64x32 (4 m-atoms x 4 n-atoms of m16n8k8 tf32).
// cp.async double-buffered K-chunks of 32.
// ---------------------------------------------------------------------------
#define AS_STRIDE 36
#define BS_STRIDE 132
#define AS_TILE (128*AS_STRIDE)
#define BS_TILE (32*BS_STRIDE)
#define GEMM_SMEM ((2*AS_TILE + 2*BS_TILE)*(int)sizeof(float))  // 70656 B

__device__ __forceinline__ void gemm_core(
    const float* __restrict__ A, int lda,
    const float* __restrict__ B, int ldb,
    int K, int m0, int n0, float* sm, float acc[4][4][4])
{
    float* As = sm;
    float* Bs = sm + 2*AS_TILE;
    const int tid  = threadIdx.x;
    const int lane = tid & 31;
    const int warp = tid >> 5;
    const int g = lane >> 2, t = lane & 3;
    const int wm = (warp >> 2) * 64;
    const int wn = (warp & 3) * 32;

    const int ar = tid >> 1;          // A tile row 0..127
    const int ac = (tid & 1) * 16;    // A tile col base (of 32)
    const int br = tid >> 3;          // B tile row 0..31
    const int bc = (tid & 7) * 16;    // B tile col base (of 128)

    const uint32_t sA = (uint32_t)__cvta_generic_to_shared(As);
    const uint32_t sB = (uint32_t)__cvta_generic_to_shared(Bs);

    // chunk 0
    {
        const float* Ap = A + (size_t)(m0 + ar) * lda + ac;
        const float* Bp = B + (size_t)br * ldb + n0 + bc;
        const uint32_t dA = sA + (uint32_t)(ar*AS_STRIDE + ac)*4u;
        const uint32_t dB = sB + (uint32_t)(br*BS_STRIDE + bc)*4u;
#pragma unroll
        for (int j = 0; j < 4; j++) cp16(dA + j*16, Ap + j*4);
#pragma unroll
        for (int j = 0; j < 4; j++) cp16(dB + j*16, Bp + j*4);
        CP_COMMIT();
    }

    for (int kb = 0; kb < K; kb += 32) {
        const int buf  = (kb >> 5) & 1;
        CP_WAIT0();
        __syncthreads();
        if (kb + 32 < K) {
            const int nb2 = buf ^ 1;
            const float* Ap = A + (size_t)(m0 + ar) * lda + kb + 32 + ac;
            const float* Bp = B + (size_t)(kb + 32 + br) * ldb + n0 + bc;
            const uint32_t dA = sA + (uint32_t)(nb2*AS_TILE + ar*AS_STRIDE + ac)*4u;
            const uint32_t dB = sB + (uint32_t)(nb2*BS_TILE + br*BS_STRIDE + bc)*4u;
#pragma unroll
            for (int j = 0; j < 4; j++) cp16(dA + j*16, Ap + j*4);
#pragma unroll
            for (int j = 0; j < 4; j++) cp16(dB + j*16, Bp + j*4);
            CP_COMMIT();
        }
        const float* Ab = As + buf*AS_TILE;
        const float* Bb = Bs + buf*BS_TILE;
#pragma unroll
        for (int ks = 0; ks < 4; ks++) {
            const int k0 = ks*8;
            uint32_t af[4][4];
#pragma unroll
            for (int ma = 0; ma < 4; ma++) {
                const int r0 = wm + ma*16;
                af[ma][0] = __float_as_uint(Ab[(r0+g  )*AS_STRIDE + k0 + t]);
                af[ma][1] = __float_as_uint(Ab[(r0+g+8)*AS_STRIDE + k0 + t]);
                af[ma][2] = __float_as_uint(Ab[(r0+g  )*AS_STRIDE + k0 + t + 4]);
                af[ma][3] = __float_as_uint(Ab[(r0+g+8)*AS_STRIDE + k0 + t + 4]);
            }
#pragma unroll
            for (int nb = 0; nb < 4; nb++) {
                uint32_t bf[2];
                const int cb = wn + nb*8 + g;
                bf[0] = __float_as_uint(Bb[(k0+t  )*BS_STRIDE + cb]);
                bf[1] = __float_as_uint(Bb[(k0+t+4)*BS_STRIDE + cb]);
#pragma unroll
                for (int ma = 0; ma < 4; ma++)
                    mma_tf32(acc[ma][nb], af[ma], bf);
            }
        }
        __syncthreads();
    }
}

// ---------------------------------------------------------------------------
// Kernel 1: QKV GEMM with scatter epilogue
// ---------------------------------------------------------------------------
__global__ void __launch_bounds__(256, 2) qkv_kernel(
    const float* __restrict__ X, const float* __restrict__ W,
    const float* __restrict__ bias)
{
    extern __shared__ float sm[];
    float acc[4][4][4];
#pragma unroll
    for (int a = 0; a < 4; a++)
#pragma unroll
        for (int b = 0; b < 4; b++)
#pragma unroll
            for (int c = 0; c < 4; c++) acc[a][b][c] = 0.f;

    const int m0 = blockIdx.y * 128;
    const int n0 = blockIdx.x * 128;
    gemm_core(X, C_, W, N3, C_, m0, n0, sm, acc);

    const int lane = threadIdx.x & 31;
    const int warp = threadIdx.x >> 5;
    const int g = lane >> 2, t = lane & 3;
    const int wm = (warp >> 2) * 64;
    const int wn = (warp & 3) * 32;

#pragma unroll
    for (int ma = 0; ma < 4; ma++) {
#pragma unroll
        for (int nb = 0; nb < 4; nb++) {
            const int col = n0 + wn + nb*8 + 2*t;
            const int part = col >> 10;
            const int cc = col & 1023;
            const int h = cc >> 6, d = cc & 63;
            float* dst = (part == 0) ? g_Q : ((part == 1) ? g_K : g_V);
            const float b0 = bias[col], b1 = bias[col + 1];
#pragma unroll
            for (int half = 0; half < 2; half++) {
                const int row = m0 + wm + ma*16 + g + half*8;
                const int bb = row >> 11, tt = row & 2047;
                const size_t idx = ((((size_t)bb*H_ + h)*T_) + tt)*D_ + d;
                float2 v;
                v.x = acc[ma][nb][half*2 + 0] + b0;
                v.y = acc[ma][nb][half*2 + 1] + b1;
                *(float2*)&dst[idx] = v;
            }
        }
    }
}

// ---------------------------------------------------------------------------
// Kernel 3: proj GEMM
// ---------------------------------------------------------------------------
__global__ void __launch_bounds__(256, 2) proj_kernel(
    const float* __restrict__ W, const float* __restrict__ bias,
    float* __restrict__ out)
{
    extern __shared__ float sm[];
    float acc[4][4][4];
#pragma unroll
    for (int a = 0; a < 4; a++)
#pragma unroll
        for (int b = 0; b < 4; b++)
#pragma unroll
            for (int c = 0; c < 4; c++) acc[a][b][c] = 0.f;

    const int m0 = blockIdx.y * 128;
    const int n0 = blockIdx.x * 128;
    gemm_core(g_O, C_, W, C_, C_, m0, n0, sm, acc);

    const int lane = threadIdx.x & 31;
    const int warp = threadIdx.x >> 5;
    const int g = lane >> 2, t = lane & 3;
    const int wm = (warp >> 2) * 64;
    const int wn = (warp & 3) * 32;

#pragma unroll
    for (int ma = 0; ma < 4; ma++) {
#pragma unroll
        for (int nb = 0; nb < 4; nb++) {
            const int col = n0 + wn + nb*8 + 2*t;
            const float b0 = bias[col], b1 = bias[col + 1];
#pragma unroll
            for (int half = 0; half < 2; half++) {
                const int row = m0 + wm + ma*16 + g + half*8;
                float2 v;
                v.x = acc[ma][nb][half*2 + 0] + b0;
                v.y = acc[ma][nb][half*2 + 1] + b1;
                *(float2*)&out[(size_t)row*C_ + col] = v;
            }
        }
    }
}

// ---------------------------------------------------------------------------
// Kernel 2: flash attention with tf32 MMA.
// Block: 128 q-rows, 8 warps, 1 m-atom (16 rows) per warp.
// Key tiles of 64 (8 n-atoms). dim=64 (8 k-steps).
// ---------------------------------------------------------------------------
#define APAD 68
#define ATTN_SMEM ((128*APAD + 64*APAD + 64*APAD + 128*APAD)*(int)sizeof(float))  // 104448

__global__ void __launch_bounds__(256, 2) attn_kernel()
{
    extern __shared__ float sm[];
    float* Qs = sm;                    // [128][APAD]  (pre-scaled by 1/8, tf32)
    float* Ks = Qs + 128*APAD;         // [64][APAD]   key-major
    float* Vs = Ks + 64*APAD;          // [64][APAD]   key-major
    float* Ps = Vs + 64*APAD;          // [128][APAD]  per-warp 16-row strips

    const int tid  = threadIdx.x;
    const int lane = tid & 31;
    const int warp = tid >> 5;
    const int g = lane >> 2, t = lane & 3;
    const int q0 = blockIdx.x * 128;
    const int bh = blockIdx.y;
    const int qr = warp * 16;          // warp's q-row base within the tile

    const float* Qg = g_Q + ((size_t)bh*T_ + q0)*D_;
    const float* Kg = g_K + (size_t)bh*T_*D_;
    const float* Vg = g_V + (size_t)bh*T_*D_;

    // Load Q tile (scaled by 1/8, tf32-rounded)
#pragma unroll
    for (int it = 0; it < 8; it++) {
        const int fi = tid + it*256;           // 2048 float4s
        const int row = fi >> 4, c4 = (fi & 15) * 4;
        float4 v = *(const float4*)(Qg + row*D_ + c4);
        v.x = f2tf(v.x*0.125f); v.y = f2tf(v.y*0.125f);
        v.z = f2tf(v.z*0.125f); v.w = f2tf(v.w*0.125f);
        *(float4*)(Qs + row*APAD + c4) = v;
    }

    float accO[8][4];
#pragma unroll
    for (int nb = 0; nb < 8; nb++)
#pragma unroll
        for (int c = 0; c < 4; c++) accO[nb][c] = 0.f;
    float m0r = -INFINITY, m1r = -INFINITY;
    float l0r = 0.f, l1r = 0.f;

    for (int kt = 0; kt < T_/64; kt++) {
        __syncthreads();
        // Load K,V tiles (64x64 each)
#pragma unroll
        for (int it = 0; it < 4; it++) {
            const int fi = tid + it*256;       // 1024 float4s
            const int row = fi >> 4, c4 = (fi & 15) * 4;
            float4 kv = *(const float4*)(Kg + (size_t)(kt*64 + row)*D_ + c4);
            kv.x = f2tf(kv.x); kv.y = f2tf(kv.y); kv.z = f2tf(kv.z); kv.w = f2tf(kv.w);
            *(float4*)(Ks + row*APAD + c4) = kv;
            float4 vv = *(const float4*)(Vg + (size_t)(kt*64 + row)*D_ + c4);
            vv.x = f2tf(vv.x); vv.y = f2tf(vv.y); vv.z = f2tf(vv.z); vv.w = f2tf(vv.w);
            *(float4*)(Vs + row*APAD + c4) = vv;
        }
        __syncthreads();

        // S = Q @ K^T   (scaled scores since Q pre-scaled)
        float sacc[8][4];
#pragma unroll
        for (int nb = 0; nb < 8; nb++)
#pragma unroll
            for (int c = 0; c < 4; c++) sacc[nb][c] = 0.f;

#pragma unroll
        for (int ks = 0; ks < 8; ks++) {
            const int k0 = ks*8;
            uint32_t af[4];
            af[0] = __float_as_uint(Qs[(qr+g  )*APAD + k0 + t]);
            af[1] = __float_as_uint(Qs[(qr+g+8)*APAD + k0 + t]);
            af[2] = __float_as_uint(Qs[(qr+g  )*APAD + k0 + t + 4]);
            af[3] = __float_as_uint(Qs[(qr+g+8)*APAD + k0 + t + 4]);
#pragma unroll
            for (int nb = 0; nb < 8; nb++) {
                uint32_t bf[2];
                bf[0] = __float_as_uint(Ks[(nb*8+g)*APAD + k0 + t]);
                bf[1] = __float_as_uint(Ks[(nb*8+g)*APAD + k0 + t + 4]);
                mma_tf32(sacc[nb], af, bf);
            }
        }

        // Online softmax on fragments. Rows: g (c0,c1), g+8 (c2,c3).
        float mx0 = -INFINITY, mx1 = -INFINITY;
#pragma unroll
        for (int nb = 0; nb < 8; nb++) {
            mx0 = fmaxf(mx0, fmaxf(sacc[nb][0], sacc[nb][1]));
            mx1 = fmaxf(mx1, fmaxf(sacc[nb][2], sacc[nb][3]));
        }
        mx0 = fmaxf(mx0, __shfl_xor_sync(0xffffffffu, mx0, 1));
        mx0 = fmaxf(mx0, __shfl_xor_sync(0xffffffffu, mx0, 2));
        mx1 = fmaxf(mx1, __shfl_xor_sync(0xffffffffu, mx1, 1));
        mx1 = fmaxf(mx1, __shfl_xor_sync(0xffffffffu, mx1, 2));

        const float mn0 = fmaxf(m0r, mx0);
        const float mn1 = fmaxf(m1r, mx1);
        const float e0 = __expf(m0r - mn0);
        const float e1 = __expf(m1r - mn1);
        m0r = mn0; m1r = mn1;

        float s0 = 0.f, s1 = 0.f;
#pragma unroll
        for (int nb = 0; nb < 8; nb++) {
            float p0 = __expf(sacc[nb][0] - mn0);
            float p1 = __expf(sacc[nb][1] - mn0);
            float p2 = __expf(sacc[nb][2] - mn1);
            float p3 = __expf(sacc[nb][3] - mn1);
            sacc[nb][0] = p0; sacc[nb][1] = p1; sacc[nb][2] = p2; sacc[nb][3] = p3;
            s0 += p0 + p1; s1 += p2 + p3;
        }
        s0 += __shfl_xor_sync(0xffffffffu, s0, 1);
        s0 += __shfl_xor_sync(0xffffffffu, s0, 2);
        s1 += __shfl_xor_sync(0xffffffffu, s1, 1);
        s1 += __shfl_xor_sync(0xffffffffu, s1, 2);
        l0r = l0r * e0 + s0;
        l1r = l1r * e1 + s1;

        // Rescale O accumulator
#pragma unroll
        for (int nb = 0; nb < 8; nb++) {
            accO[nb][0] *= e0; accO[nb][1] *= e0;
            accO[nb][2] *= e1; accO[nb][3] *= e1;
        }

        // Stage P into per-warp smem region (tf32-rounded)
#pragma unroll
        for (int nb = 0; nb < 8; nb++) {
            float2 p01; p01.x = f2tf(sacc[nb][0]); p01.y = f2tf(sacc[nb][1]);
            float2 p23; p23.x = f2tf(sacc[nb][2]); p23.y = f2tf(sacc[nb][3]);
            *(float2*)(Ps + (qr+g  )*APAD + nb*8 + 2*t) = p01;
            *(float2*)(Ps + (qr+g+8)*APAD + nb*8 + 2*t) = p23;
        }
        __syncwarp();

        // O += P @ V
#pragma unroll
        for (int ks = 0; ks < 8; ks++) {
            const int k0 = ks*8;
            uint32_t af[4];
            af[0] = __float_as_uint(Ps[(qr+g  )*APAD + k0 + t]);
            af[1] = __float_as_uint(Ps[(qr+g+8)*APAD + k0 + t]);
            af[2] = __float_as_uint(Ps[(qr+g  )*APAD + k0 + t + 4]);
            af[3] = __float_as_uint(Ps[(qr+g+8)*APAD + k0 + t + 4]);
#pragma unroll
            for (int nb = 0; nb < 8; nb++) {
                uint32_t bf[2];
                bf[0] = __float_as_uint(Vs[(k0+t  )*APAD + nb*8 + g]);
                bf[1] = __float_as_uint(Vs[(k0+t+4)*APAD + nb*8 + g]);
                mma_tf32(accO[nb], af, bf);
            }
        }
        __syncwarp();
    }

    // Epilogue: normalize, write to g_O[B,T,C]
    const float inv0 = 1.f / l0r;
    const float inv1 = 1.f / l1r;
    const int b = bh >> 4, h = bh & 15;
    const int r0 = q0 + qr + g;
#pragma unroll
    for (int nb = 0; nb < 8; nb++) {
        const int col = h*D_ + nb*8 + 2*t;
        float2 v0; v0.x = accO[nb][0]*inv0; v0.y = accO[nb][1]*inv0;
        float2 v1; v1.x = accO[nb][2]*inv1; v1.y = accO[nb][3]*inv1;
        *(float2*)&g_O[((size_t)b*T_ + r0    )*C_ + col] = v0;
        *(float2*)&g_O[((size_t)b*T_ + r0 + 8)*C_ + col] = v1;
    }
}

// ---------------------------------------------------------------------------
// Launch
// ---------------------------------------------------------------------------
extern "C" void kernel_launch(void* const* d_in, const int* in_sizes, int n_in,
                              void* d_out, int out_size)
{
    (void)in_sizes; (void)n_in; (void)out_size;
    const float* X      = (const float*)d_in[0];
    const float* W_qkv  = (const float*)d_in[1];
    const float* b_qkv  = (const float*)d_in[2];
    const float* W_proj = (const float*)d_in[3];
    const float* b_proj = (const float*)d_in[4];
    float* out = (float*)d_out;

    cudaFuncSetAttribute(qkv_kernel,  cudaFuncAttributeMaxDynamicSharedMemorySize, GEMM_SMEM);
    cudaFuncSetAttribute(proj_kernel, cudaFuncAttributeMaxDynamicSharedMemorySize, GEMM_SMEM);
    cudaFuncSetAttribute(attn_kernel, cudaFuncAttributeMaxDynamicSharedMemorySize, ATTN_SMEM);

    dim3 g1(N3/128, M_/128);            // (24, 64)
    qkv_kernel<<<g1, 256, GEMM_SMEM>>>(X, W_qkv, b_qkv);

    dim3 g2(T_/128, B_*H_);             // (16, 64)
    attn_kernel<<<g2, 256, ATTN_SMEM>>>();

    dim3 g3(C_/128, M_/128);            // (8, 64)
    proj_kernel<<<g3, 256, GEMM_SMEM>>>(W_proj, b_proj, out);
}